// round 1
// baseline (speedup 1.0000x reference)
#include <cuda_runtime.h>
#include <cuda_bf16.h>

// Problem constants (match reference)
#define NUM_U 200000
#define NUM_I 100000
#define DIM   64
#define KTYP  4

// Scratch ping-pong buffers for layer outputs (type-sequential processing).
// __device__ globals are the allowed scratch mechanism (no cudaMalloc).
__device__ float g_ubuf1[(size_t)NUM_U * DIM];
__device__ float g_ubuf2[(size_t)NUM_U * DIM];
__device__ float g_ibuf1[(size_t)NUM_I * DIM];
__device__ float g_ibuf2[(size_t)NUM_I * DIM];

// ---------------------------------------------------------------------------
// COO SpMM: dst[rows[e], :] += vals[e] * src[cols[e], :]
// 16 threads per edge, one float4 per lane (64 floats per row).
// Scatter via vectorized reduction (red.global.add.v4.f32, sm_90+).
// ---------------------------------------------------------------------------
__global__ void spmm_kernel(const int* __restrict__ rows,
                            const int* __restrict__ cols,
                            const float* __restrict__ vals,
                            const float* __restrict__ src,
                            float* __restrict__ dst,
                            int nE)
{
    long long g = (long long)blockIdx.x * blockDim.x + threadIdx.x;
    int edge = (int)(g >> 4);
    int lane = (int)(g & 15);
    if (edge >= nE) return;

    int   r = __ldg(rows + edge);
    int   c = __ldg(cols + edge);
    float v = __ldg(vals + edge);

    const float4* sp = reinterpret_cast<const float4*>(src + (size_t)c * DIM);
    float4 s = __ldg(sp + lane);

    float* p = dst + (size_t)r * DIM + lane * 4;
    asm volatile("red.global.add.v4.f32 [%0], {%1, %2, %3, %4};"
                 :: "l"(p), "f"(v * s.x), "f"(v * s.y), "f"(v * s.z), "f"(v * s.w)
                 : "memory");
}

// ---------------------------------------------------------------------------
// Fused combine: out[row, out_off + j] = relu( ((e0+e1+e2)/3 @ W)[row, j] )
// One warp per row. W (64x64) staged in shared memory.
// ---------------------------------------------------------------------------
__global__ void combine_gemm_kernel(const float* __restrict__ e0,
                                    const float* __restrict__ e1,
                                    const float* __restrict__ e2,
                                    const float* __restrict__ W,
                                    float* __restrict__ out,
                                    int nrows, int out_stride, int out_off)
{
    __shared__ float Ws[DIM][DIM];
    for (int i = threadIdx.x; i < DIM * DIM; i += blockDim.x)
        Ws[i >> 6][i & 63] = W[i];
    __syncthreads();

    int warp = threadIdx.x >> 5;
    int lane = threadIdx.x & 31;
    int warps_per_block = blockDim.x >> 5;

    for (int row = blockIdx.x * warps_per_block + warp; row < nrows;
         row += (long long)gridDim.x * warps_per_block) {
        size_t base = (size_t)row * DIM;
        const float inv3 = 1.0f / 3.0f;
        float a_lo = (e0[base + lane]      + e1[base + lane]      + e2[base + lane])      * inv3;
        float a_hi = (e0[base + 32 + lane] + e1[base + 32 + lane] + e2[base + 32 + lane]) * inv3;

        float acc0 = 0.0f, acc1 = 0.0f;
#pragma unroll
        for (int d = 0; d < 32; d++) {
            float ad = __shfl_sync(0xffffffffu, a_lo, d);
            acc0 += ad * Ws[d][lane];
            acc1 += ad * Ws[d][lane + 32];
        }
#pragma unroll
        for (int d = 0; d < 32; d++) {
            float ad = __shfl_sync(0xffffffffu, a_hi, d);
            acc0 += ad * Ws[d + 32][lane];
            acc1 += ad * Ws[d + 32][lane + 32];
        }

        float* o = out + (size_t)row * out_stride + out_off;
        o[lane]      = fmaxf(acc0, 0.0f);
        o[lane + 32] = fmaxf(acc1, 0.0f);
    }
}

static inline void launch_spmm(const void* rows, const void* cols, const void* vals,
                               const float* src, float* dst, int nE)
{
    int threads = 256;
    long long total = (long long)nE * 16;
    int blocks = (int)((total + threads - 1) / threads);
    spmm_kernel<<<blocks, threads>>>((const int*)rows, (const int*)cols,
                                     (const float*)vals, src, dst, nE);
}

extern "C" void kernel_launch(void* const* d_in, const int* in_sizes, int n_in,
                              void* d_out, int out_size)
{
    // Inputs (metadata order = reference signature order)
    const void* u2u_r  = d_in[0];  const void* u2u_c  = d_in[1];  const void* u2u_v  = d_in[2];
    const void* u2i_r0 = d_in[3];  const void* u2i_c0 = d_in[4];  const void* u2i_v0 = d_in[5];
    const void* u2i_r1 = d_in[6];  const void* u2i_c1 = d_in[7];  const void* u2i_v1 = d_in[8];
    const void* i2u_r0 = d_in[9];  const void* i2u_c0 = d_in[10]; const void* i2u_v0 = d_in[11];
    const void* i2u_r1 = d_in[12]; const void* i2u_c1 = d_in[13]; const void* i2u_v1 = d_in[14];
    const void* i2i_r  = d_in[15]; const void* i2i_c  = d_in[16]; const void* i2i_v  = d_in[17];
    const float* user_embs = (const float*)d_in[18];  // [K, U, D]
    const float* item_embs = (const float*)d_in[19];  // [K, I, D]
    const float* W_u       = (const float*)d_in[20];  // [K, D, D]
    const float* W_v       = (const float*)d_in[21];  // [K, D, D]

    const int E_uu = in_sizes[0];
    const int E_ui0 = in_sizes[3], E_ui1 = in_sizes[6];
    const int E_iu0 = in_sizes[9], E_iu1 = in_sizes[12];
    const int E_ii = in_sizes[15];

    float* out_user = (float*)d_out;                              // [U, K*D]
    float* out_item = (float*)d_out + (size_t)NUM_U * (KTYP * DIM); // [I, K*D]

    float *ub1, *ub2, *ib1, *ib2;
    cudaGetSymbolAddress((void**)&ub1, g_ubuf1);
    cudaGetSymbolAddress((void**)&ub2, g_ubuf2);
    cudaGetSymbolAddress((void**)&ib1, g_ibuf1);
    cudaGetSymbolAddress((void**)&ib2, g_ibuf2);

    const size_t UBYTES = (size_t)NUM_U * DIM * sizeof(float);
    const size_t IBYTES = (size_t)NUM_I * DIM * sizeof(float);

    for (int k = 0; k < KTYP; k++) {
        const float* ue0 = user_embs + (size_t)k * NUM_U * DIM;
        const float* ie0 = item_embs + (size_t)k * NUM_I * DIM;

        // ---------------- layer 1: (ue0, ie0) -> (ub1, ib1) ----------------
        cudaMemsetAsync(ub1, 0, UBYTES, 0);
        cudaMemsetAsync(ib1, 0, IBYTES, 0);
        launch_spmm(u2u_r,  u2u_c,  u2u_v,  ue0, ub1, E_uu);
        launch_spmm(u2i_r0, u2i_c0, u2i_v0, ie0, ub1, E_ui0);
        launch_spmm(u2i_r1, u2i_c1, u2i_v1, ie0, ub1 + (size_t)(NUM_U / 2) * DIM, E_ui1);
        launch_spmm(i2i_r,  i2i_c,  i2i_v,  ie0, ib1, E_ii);
        launch_spmm(i2u_r0, i2u_c0, i2u_v0, ue0, ib1, E_iu0);
        launch_spmm(i2u_r1, i2u_c1, i2u_v1, ue0, ib1 + (size_t)(NUM_I / 2) * DIM, E_iu1);

        // ---------------- layer 2: (ub1, ib1) -> (ub2, ib2) ----------------
        cudaMemsetAsync(ub2, 0, UBYTES, 0);
        cudaMemsetAsync(ib2, 0, IBYTES, 0);
        launch_spmm(u2u_r,  u2u_c,  u2u_v,  ub1, ub2, E_uu);
        launch_spmm(u2i_r0, u2i_c0, u2i_v0, ib1, ub2, E_ui0);
        launch_spmm(u2i_r1, u2i_c1, u2i_v1, ib1, ub2 + (size_t)(NUM_U / 2) * DIM, E_ui1);
        launch_spmm(i2i_r,  i2i_c,  i2i_v,  ib1, ib2, E_ii);
        launch_spmm(i2u_r0, i2u_c0, i2u_v0, ub1, ib2, E_iu0);
        launch_spmm(i2u_r1, i2u_c1, i2u_v1, ub1, ib2 + (size_t)(NUM_I / 2) * DIM, E_iu1);

        // ---------------- combine: mean over layers, GEMM, ReLU ------------
        {
            int threads = 256;                    // 8 warps -> 8 rows per block
            int blocks_u = (NUM_U + 7) / 8;
            int blocks_i = (NUM_I + 7) / 8;
            combine_gemm_kernel<<<blocks_u, threads>>>(ue0, ub1, ub2,
                                                       W_u + (size_t)k * DIM * DIM,
                                                       out_user, NUM_U, KTYP * DIM, k * DIM);
            combine_gemm_kernel<<<blocks_i, threads>>>(ie0, ib1, ib2,
                                                       W_v + (size_t)k * DIM * DIM,
                                                       out_item, NUM_I, KTYP * DIM, k * DIM);
        }
    }
}

// round 2
// speedup vs baseline: 1.5950x; 1.5950x over previous
#include <cuda_runtime.h>
#include <cuda_bf16.h>

#define NUM_U 200000
#define NUM_I 100000
#define DIM   64
#define KTYP  4
#define E_A   1000000   // u2u
#define E_B   3200000   // item->user (u2i_* folds merged)
#define E_C   1000000   // i2i
#define E_D   3200000   // user->item (i2u_* folds merged)

// ---- scratch (device globals; no allocation allowed) ----
__device__ float g_ub1[(size_t)NUM_U * DIM];
__device__ float g_ub2[(size_t)NUM_U * DIM];
__device__ float g_ib1[(size_t)NUM_I * DIM];
__device__ float g_ib2[(size_t)NUM_I * DIM];

__device__ float2 g_packA[E_A];
__device__ float2 g_packB[E_B];
__device__ float2 g_packC[E_C];
__device__ float2 g_packD[E_D];

__device__ int g_offA[NUM_U + 1];
__device__ int g_offB[NUM_U + 1];
__device__ int g_offC[NUM_I + 1];
__device__ int g_offD[NUM_I + 1];
__device__ int g_curA[NUM_U];
__device__ int g_curB[NUM_U];
__device__ int g_curC[NUM_I];
__device__ int g_curD[NUM_I];
__device__ int g_bsums[256];

// ---------------------------------------------------------------------------
// CSR build: histogram -> 3-phase exclusive scan -> stable-ish scatter
// ---------------------------------------------------------------------------
__global__ void hist_kernel(const int* __restrict__ rows, int nE,
                            int* __restrict__ counts, int roff)
{
    int i = blockIdx.x * blockDim.x + threadIdx.x;
    if (i < nE) atomicAdd(&counts[rows[i] + roff], 1);
}

__global__ void scan_phase1(const int* __restrict__ counts, int n,
                            int* __restrict__ bsums)
{
    __shared__ int sh[1024];
    int i = blockIdx.x * 1024 + threadIdx.x;
    sh[threadIdx.x] = (i < n) ? counts[i] : 0;
    __syncthreads();
    for (int s = 512; s > 0; s >>= 1) {
        if (threadIdx.x < s) sh[threadIdx.x] += sh[threadIdx.x + s];
        __syncthreads();
    }
    if (threadIdx.x == 0) bsums[blockIdx.x] = sh[0];
}

__global__ void scan_phase2(int* __restrict__ bsums, int nb,
                            int* __restrict__ off, int n)
{
    __shared__ int sh[256];
    int v = (threadIdx.x < nb) ? bsums[threadIdx.x] : 0;
    sh[threadIdx.x] = v;
    __syncthreads();
    for (int d = 1; d < 256; d <<= 1) {
        int t = (threadIdx.x >= d) ? sh[threadIdx.x - d] : 0;
        __syncthreads();
        sh[threadIdx.x] += t;
        __syncthreads();
    }
    if (threadIdx.x < nb) bsums[threadIdx.x] = sh[threadIdx.x] - v;  // exclusive
    if (threadIdx.x == 255) off[n] = sh[255];                        // total
}

__global__ void scan_phase3(const int* __restrict__ counts, int n,
                            const int* __restrict__ bsums, int* __restrict__ off)
{
    __shared__ int sh[1024];
    int i = blockIdx.x * 1024 + threadIdx.x;
    int v = (i < n) ? counts[i] : 0;
    sh[threadIdx.x] = v;
    __syncthreads();
    for (int d = 1; d < 1024; d <<= 1) {
        int t = (threadIdx.x >= d) ? sh[threadIdx.x - d] : 0;
        __syncthreads();
        sh[threadIdx.x] += t;
        __syncthreads();
    }
    if (i < n) off[i] = sh[threadIdx.x] - v + bsums[blockIdx.x];
}

__global__ void scatter_kernel(const int* __restrict__ rows,
                               const int* __restrict__ cols,
                               const float* __restrict__ vals, int nE,
                               int* __restrict__ cur, float2* __restrict__ pack,
                               int roff)
{
    int i = blockIdx.x * blockDim.x + threadIdx.x;
    if (i < nE) {
        int r = rows[i] + roff;
        int pos = atomicAdd(&cur[r], 1);
        pack[pos] = make_float2(__int_as_float(cols[i]), vals[i]);
    }
}

// ---------------------------------------------------------------------------
// Dual-source CSR SpMM: dst[r,:] = sum_A val*srcA[col,:] + sum_B val*srcB[col,:]
// One warp per row, float2 per lane, register accumulation, single store.
// ---------------------------------------------------------------------------
__global__ void csr_spmm_dual(const int* __restrict__ offA,
                              const float2* __restrict__ packA,
                              const float* __restrict__ srcA,
                              const int* __restrict__ offB,
                              const float2* __restrict__ packB,
                              const float* __restrict__ srcB,
                              float* __restrict__ dst, int nrows)
{
    int w = (blockIdx.x * blockDim.x + threadIdx.x) >> 5;
    int lane = threadIdx.x & 31;
    if (w >= nrows) return;

    float ax = 0.0f, ay = 0.0f;

    int s = __ldg(offA + w), e = __ldg(offA + w + 1);
    for (int i = s; i < e; i++) {
        float2 p = __ldg(packA + i);
        const float2* sp = reinterpret_cast<const float2*>(
            srcA + (size_t)__float_as_int(p.x) * DIM);
        float2 sv = __ldg(sp + lane);
        ax = fmaf(p.y, sv.x, ax);
        ay = fmaf(p.y, sv.y, ay);
    }

    s = __ldg(offB + w); e = __ldg(offB + w + 1);
    for (int i = s; i < e; i++) {
        float2 p = __ldg(packB + i);
        const float2* sp = reinterpret_cast<const float2*>(
            srcB + (size_t)__float_as_int(p.x) * DIM);
        float2 sv = __ldg(sp + lane);
        ax = fmaf(p.y, sv.x, ax);
        ay = fmaf(p.y, sv.y, ay);
    }

    reinterpret_cast<float2*>(dst + (size_t)w * DIM)[lane] = make_float2(ax, ay);
}

// ---------------------------------------------------------------------------
// Fused combine: out[row, off+j] = relu( ((e0+e1+e2)/3 @ W)[row, j] )
// ---------------------------------------------------------------------------
__global__ void combine_gemm_kernel(const float* __restrict__ e0,
                                    const float* __restrict__ e1,
                                    const float* __restrict__ e2,
                                    const float* __restrict__ W,
                                    float* __restrict__ out,
                                    int nrows, int out_stride, int out_off)
{
    __shared__ float Ws[DIM][DIM];
    for (int i = threadIdx.x; i < DIM * DIM; i += blockDim.x)
        Ws[i >> 6][i & 63] = W[i];
    __syncthreads();

    int warp = threadIdx.x >> 5;
    int lane = threadIdx.x & 31;
    int wpb = blockDim.x >> 5;
    int row = blockIdx.x * wpb + warp;
    if (row >= nrows) return;

    size_t base = (size_t)row * DIM;
    const float inv3 = 1.0f / 3.0f;
    float a_lo = (e0[base + lane]      + e1[base + lane]      + e2[base + lane])      * inv3;
    float a_hi = (e0[base + 32 + lane] + e1[base + 32 + lane] + e2[base + 32 + lane]) * inv3;

    float acc0 = 0.0f, acc1 = 0.0f;
#pragma unroll
    for (int d = 0; d < 32; d++) {
        float ad = __shfl_sync(0xffffffffu, a_lo, d);
        acc0 += ad * Ws[d][lane];
        acc1 += ad * Ws[d][lane + 32];
    }
#pragma unroll
    for (int d = 0; d < 32; d++) {
        float ad = __shfl_sync(0xffffffffu, a_hi, d);
        acc0 += ad * Ws[d + 32][lane];
        acc1 += ad * Ws[d + 32][lane + 32];
    }

    float* o = out + (size_t)row * out_stride + out_off;
    o[lane]      = fmaxf(acc0, 0.0f);
    o[lane + 32] = fmaxf(acc1, 0.0f);
}

// ---------------------------------------------------------------------------
// Host helpers
// ---------------------------------------------------------------------------
static void build_csr(const void* rows0, const void* cols0, const void* vals0, int n0, int roff0,
                      const void* rows1, const void* cols1, const void* vals1, int n1, int roff1,
                      int* cur, int* off, float2* pack, int nrows, int* bsums)
{
    cudaMemsetAsync(cur, 0, (size_t)nrows * sizeof(int), 0);
    hist_kernel<<<(n0 + 255) / 256, 256>>>((const int*)rows0, n0, cur, roff0);
    if (rows1)
        hist_kernel<<<(n1 + 255) / 256, 256>>>((const int*)rows1, n1, cur, roff1);

    int nb = (nrows + 1023) / 1024;
    scan_phase1<<<nb, 1024>>>(cur, nrows, bsums);
    scan_phase2<<<1, 256>>>(bsums, nb, off, nrows);
    scan_phase3<<<nb, 1024>>>(cur, nrows, bsums, off);

    cudaMemcpyAsync(cur, off, (size_t)nrows * sizeof(int),
                    cudaMemcpyDeviceToDevice, 0);

    scatter_kernel<<<(n0 + 255) / 256, 256>>>((const int*)rows0, (const int*)cols0,
                                              (const float*)vals0, n0, cur, pack, roff0);
    if (rows1)
        scatter_kernel<<<(n1 + 255) / 256, 256>>>((const int*)rows1, (const int*)cols1,
                                                  (const float*)vals1, n1, cur, pack, roff1);
}

extern "C" void kernel_launch(void* const* d_in, const int* in_sizes, int n_in,
                              void* d_out, int out_size)
{
    const void* u2u_r  = d_in[0];  const void* u2u_c  = d_in[1];  const void* u2u_v  = d_in[2];
    const void* u2i_r0 = d_in[3];  const void* u2i_c0 = d_in[4];  const void* u2i_v0 = d_in[5];
    const void* u2i_r1 = d_in[6];  const void* u2i_c1 = d_in[7];  const void* u2i_v1 = d_in[8];
    const void* i2u_r0 = d_in[9];  const void* i2u_c0 = d_in[10]; const void* i2u_v0 = d_in[11];
    const void* i2u_r1 = d_in[12]; const void* i2u_c1 = d_in[13]; const void* i2u_v1 = d_in[14];
    const void* i2i_r  = d_in[15]; const void* i2i_c  = d_in[16]; const void* i2i_v  = d_in[17];
    const float* user_embs = (const float*)d_in[18];
    const float* item_embs = (const float*)d_in[19];
    const float* W_u       = (const float*)d_in[20];
    const float* W_v       = (const float*)d_in[21];

    const int E_uu  = in_sizes[0];
    const int E_ui0 = in_sizes[3], E_ui1 = in_sizes[6];
    const int E_iu0 = in_sizes[9], E_iu1 = in_sizes[12];
    const int E_ii  = in_sizes[15];

    float* out_user = (float*)d_out;
    float* out_item = (float*)d_out + (size_t)NUM_U * (KTYP * DIM);

    float *ub1, *ub2, *ib1, *ib2;
    float2 *pA, *pB, *pC, *pD;
    int *oA, *oB, *oC, *oD, *cA, *cB, *cC, *cD, *bs;
    cudaGetSymbolAddress((void**)&ub1, g_ub1);
    cudaGetSymbolAddress((void**)&ub2, g_ub2);
    cudaGetSymbolAddress((void**)&ib1, g_ib1);
    cudaGetSymbolAddress((void**)&ib2, g_ib2);
    cudaGetSymbolAddress((void**)&pA, g_packA);
    cudaGetSymbolAddress((void**)&pB, g_packB);
    cudaGetSymbolAddress((void**)&pC, g_packC);
    cudaGetSymbolAddress((void**)&pD, g_packD);
    cudaGetSymbolAddress((void**)&oA, g_offA);
    cudaGetSymbolAddress((void**)&oB, g_offB);
    cudaGetSymbolAddress((void**)&oC, g_offC);
    cudaGetSymbolAddress((void**)&oD, g_offD);
    cudaGetSymbolAddress((void**)&cA, g_curA);
    cudaGetSymbolAddress((void**)&cB, g_curB);
    cudaGetSymbolAddress((void**)&cC, g_curC);
    cudaGetSymbolAddress((void**)&cD, g_curD);
    cudaGetSymbolAddress((void**)&bs, g_bsums);

    // ---- build the 4 CSR structures (per replay; edge lists shared by all k) ----
    build_csr(u2u_r, u2u_c, u2u_v, E_uu, 0,
              nullptr, nullptr, nullptr, 0, 0, cA, oA, pA, NUM_U, bs);
    build_csr(u2i_r0, u2i_c0, u2i_v0, E_ui0, 0,
              u2i_r1, u2i_c1, u2i_v1, E_ui1, NUM_U / 2, cB, oB, pB, NUM_U, bs);
    build_csr(i2i_r, i2i_c, i2i_v, E_ii, 0,
              nullptr, nullptr, nullptr, 0, 0, cC, oC, pC, NUM_I, bs);
    build_csr(i2u_r0, i2u_c0, i2u_v0, E_iu0, 0,
              i2u_r1, i2u_c1, i2u_v1, E_iu1, NUM_I / 2, cD, oD, pD, NUM_I, bs);

    const int TPB = 256;                       // 8 warps = 8 rows / block
    const int gu = (NUM_U + 7) / 8;
    const int gi = (NUM_I + 7) / 8;

    for (int k = 0; k < KTYP; k++) {
        const float* ue0 = user_embs + (size_t)k * NUM_U * DIM;
        const float* ie0 = item_embs + (size_t)k * NUM_I * DIM;

        // layer 1
        csr_spmm_dual<<<gu, TPB>>>(oA, pA, ue0, oB, pB, ie0, ub1, NUM_U);
        csr_spmm_dual<<<gi, TPB>>>(oC, pC, ie0, oD, pD, ue0, ib1, NUM_I);
        // layer 2
        csr_spmm_dual<<<gu, TPB>>>(oA, pA, ub1, oB, pB, ib1, ub2, NUM_U);
        csr_spmm_dual<<<gi, TPB>>>(oC, pC, ib1, oD, pD, ub1, ib2, NUM_I);

        // combine: mean of {layer0, layer1, layer2} @ W, ReLU
        combine_gemm_kernel<<<(NUM_U + 7) / 8, 256>>>(ue0, ub1, ub2,
                                                      W_u + (size_t)k * DIM * DIM,
                                                      out_user, NUM_U, KTYP * DIM, k * DIM);
        combine_gemm_kernel<<<(NUM_I + 7) / 8, 256>>>(ie0, ib1, ib2,
                                                      W_v + (size_t)k * DIM * DIM,
                                                      out_item, NUM_I, KTYP * DIM, k * DIM);
    }
}

// round 3
// speedup vs baseline: 1.9896x; 1.2474x over previous
#include <cuda_runtime.h>
#include <cuda_fp16.h>
#include <cuda_bf16.h>

#define NUM_U 200000
#define NUM_I 100000
#define DIM   64
#define KTYP  4
#define E_A   1000000   // u2u
#define E_B   3200000   // u2i folds merged (item -> user agg)
#define E_C   1000000   // i2i
#define E_D   3200000   // i2u folds merged (user -> item agg)

// ---- scratch (device globals; no allocation allowed) ----
__device__ __half2 g_ueh[(size_t)KTYP * NUM_U * (DIM / 2)];   // 102.4 MB
__device__ __half2 g_ieh[(size_t)KTYP * NUM_I * (DIM / 2)];   //  51.2 MB
__device__ __half2 g_ub1h[(size_t)NUM_U * (DIM / 2)];         //  25.6 MB
__device__ __half2 g_ib1h[(size_t)NUM_I * (DIM / 2)];         //  12.8 MB

__device__ float2 g_packA[E_A];
__device__ float2 g_packB[E_B];
__device__ float2 g_packC[E_C];
__device__ float2 g_packD[E_D];

__device__ int g_offA[NUM_U + 1];
__device__ int g_offB[NUM_U + 1];
__device__ int g_offC[NUM_I + 1];
__device__ int g_offD[NUM_I + 1];
__device__ int g_curA[NUM_U];
__device__ int g_curB[NUM_U];
__device__ int g_curC[NUM_I];
__device__ int g_curD[NUM_I];
__device__ int g_bsums[256];

// ---------------------------------------------------------------------------
// fp32 -> half2 conversion (pairs)
// ---------------------------------------------------------------------------
__global__ void convert_kernel(const float2* __restrict__ src,
                               __half2* __restrict__ dst, long long npairs)
{
    long long i = (long long)blockIdx.x * blockDim.x + threadIdx.x;
    if (i < npairs) {
        float2 f = __ldg(src + i);
        dst[i] = __floats2half2_rn(f.x, f.y);
    }
}

// ---------------------------------------------------------------------------
// CSR build: histogram -> 3-phase exclusive scan -> scatter
// ---------------------------------------------------------------------------
__global__ void hist_kernel(const int* __restrict__ rows, int nE,
                            int* __restrict__ counts, int roff)
{
    int i = blockIdx.x * blockDim.x + threadIdx.x;
    if (i < nE) atomicAdd(&counts[rows[i] + roff], 1);
}

__global__ void scan_phase1(const int* __restrict__ counts, int n,
                            int* __restrict__ bsums)
{
    __shared__ int sh[1024];
    int i = blockIdx.x * 1024 + threadIdx.x;
    sh[threadIdx.x] = (i < n) ? counts[i] : 0;
    __syncthreads();
    for (int s = 512; s > 0; s >>= 1) {
        if (threadIdx.x < s) sh[threadIdx.x] += sh[threadIdx.x + s];
        __syncthreads();
    }
    if (threadIdx.x == 0) bsums[blockIdx.x] = sh[0];
}

__global__ void scan_phase2(int* __restrict__ bsums, int nb,
                            int* __restrict__ off, int n)
{
    __shared__ int sh[256];
    int v = (threadIdx.x < nb) ? bsums[threadIdx.x] : 0;
    sh[threadIdx.x] = v;
    __syncthreads();
    for (int d = 1; d < 256; d <<= 1) {
        int t = (threadIdx.x >= d) ? sh[threadIdx.x - d] : 0;
        __syncthreads();
        sh[threadIdx.x] += t;
        __syncthreads();
    }
    if (threadIdx.x < nb) bsums[threadIdx.x] = sh[threadIdx.x] - v;  // exclusive
    if (threadIdx.x == 255) off[n] = sh[255];
}

__global__ void scan_phase3(const int* __restrict__ counts, int n,
                            const int* __restrict__ bsums, int* __restrict__ off)
{
    __shared__ int sh[1024];
    int i = blockIdx.x * 1024 + threadIdx.x;
    int v = (i < n) ? counts[i] : 0;
    sh[threadIdx.x] = v;
    __syncthreads();
    for (int d = 1; d < 1024; d <<= 1) {
        int t = (threadIdx.x >= d) ? sh[threadIdx.x - d] : 0;
        __syncthreads();
        sh[threadIdx.x] += t;
        __syncthreads();
    }
    if (i < n) off[i] = sh[threadIdx.x] - v + bsums[blockIdx.x];
}

__global__ void scatter_kernel(const int* __restrict__ rows,
                               const int* __restrict__ cols,
                               const float* __restrict__ vals, int nE,
                               int* __restrict__ cur, float2* __restrict__ pack,
                               int roff)
{
    int i = blockIdx.x * blockDim.x + threadIdx.x;
    if (i < nE) {
        int r = rows[i] + roff;
        int pos = atomicAdd(&cur[r], 1);
        pack[pos] = make_float2(__int_as_float(cols[i]), vals[i]);
    }
}

// ---------------------------------------------------------------------------
// Layer-1 dual-source CSR SpMM (half gather, fp32 accumulate, half store)
// One warp per row; lane covers dims (2*lane, 2*lane+1).
// ---------------------------------------------------------------------------
__global__ void spmm_dual_h(const int* __restrict__ offA,
                            const float2* __restrict__ packA,
                            const __half2* __restrict__ srcA,
                            const int* __restrict__ offB,
                            const float2* __restrict__ packB,
                            const __half2* __restrict__ srcB,
                            __half2* __restrict__ dst, int nrows)
{
    int w = (blockIdx.x * blockDim.x + threadIdx.x) >> 5;
    int lane = threadIdx.x & 31;
    if (w >= nrows) return;

    float ax = 0.0f, ay = 0.0f;

    int s = __ldg(offA + w), e = __ldg(offA + w + 1);
    for (int i = s; i < e; i++) {
        float2 p = __ldg(packA + i);
        float2 sv = __half22float2(__ldg(srcA + (size_t)__float_as_int(p.x) * 32 + lane));
        ax = fmaf(p.y, sv.x, ax);
        ay = fmaf(p.y, sv.y, ay);
    }
    s = __ldg(offB + w); e = __ldg(offB + w + 1);
    for (int i = s; i < e; i++) {
        float2 p = __ldg(packB + i);
        float2 sv = __half22float2(__ldg(srcB + (size_t)__float_as_int(p.x) * 32 + lane));
        ax = fmaf(p.y, sv.x, ax);
        ay = fmaf(p.y, sv.y, ay);
    }

    dst[(size_t)w * 32 + lane] = __floats2half2_rn(ax, ay);
}

// ---------------------------------------------------------------------------
// Fused layer-2 SpMM + layer-mean + 64x64 GEMM + ReLU -> fp32 output slice
// ---------------------------------------------------------------------------
__global__ void spmm_fused(const int* __restrict__ offA,
                           const float2* __restrict__ packA,
                           const __half2* __restrict__ srcA,
                           const int* __restrict__ offB,
                           const float2* __restrict__ packB,
                           const __half2* __restrict__ srcB,
                           const float* __restrict__ e0,    // fp32 layer-0 [nrows*64]
                           const __half2* __restrict__ e1,  // half layer-1 [nrows*32]
                           const float* __restrict__ W,     // [64,64]
                           float* __restrict__ out,
                           int nrows, int out_stride, int out_off)
{
    __shared__ float Ws[DIM][DIM];
    for (int i = threadIdx.x; i < DIM * DIM; i += blockDim.x)
        Ws[i >> 6][i & 63] = W[i];
    __syncthreads();

    int w = (blockIdx.x * blockDim.x + threadIdx.x) >> 5;
    int lane = threadIdx.x & 31;
    if (w >= nrows) return;

    float ax = 0.0f, ay = 0.0f;

    int s = __ldg(offA + w), e = __ldg(offA + w + 1);
    for (int i = s; i < e; i++) {
        float2 p = __ldg(packA + i);
        float2 sv = __half22float2(__ldg(srcA + (size_t)__float_as_int(p.x) * 32 + lane));
        ax = fmaf(p.y, sv.x, ax);
        ay = fmaf(p.y, sv.y, ay);
    }
    s = __ldg(offB + w); e = __ldg(offB + w + 1);
    for (int i = s; i < e; i++) {
        float2 p = __ldg(packB + i);
        float2 sv = __half22float2(__ldg(srcB + (size_t)__float_as_int(p.x) * 32 + lane));
        ax = fmaf(p.y, sv.x, ax);
        ay = fmaf(p.y, sv.y, ay);
    }

    // layer mean: (e0 + e1 + e2) / 3   (e2 = fresh fp32 accumulators)
    const float inv3 = 1.0f / 3.0f;
    float2 f0 = __ldg(reinterpret_cast<const float2*>(e0 + (size_t)w * DIM) + lane);
    float2 f1 = __half22float2(__ldg(e1 + (size_t)w * 32 + lane));
    float m0 = (f0.x + f1.x + ax) * inv3;
    float m1 = (f0.y + f1.y + ay) * inv3;

    // GEMM via shfl broadcast: lane computes out cols (lane, lane+32)
    float acc0 = 0.0f, acc1 = 0.0f;
#pragma unroll
    for (int l = 0; l < 32; l++) {
        float b0 = __shfl_sync(0xffffffffu, m0, l);
        float b1 = __shfl_sync(0xffffffffu, m1, l);
        acc0 += b0 * Ws[2 * l][lane]      + b1 * Ws[2 * l + 1][lane];
        acc1 += b0 * Ws[2 * l][lane + 32] + b1 * Ws[2 * l + 1][lane + 32];
    }

    float* o = out + (size_t)w * out_stride + out_off;
    o[lane]      = fmaxf(acc0, 0.0f);
    o[lane + 32] = fmaxf(acc1, 0.0f);
}

// ---------------------------------------------------------------------------
// Host helpers
// ---------------------------------------------------------------------------
static void build_csr(const void* rows0, const void* cols0, const void* vals0, int n0, int roff0,
                      const void* rows1, const void* cols1, const void* vals1, int n1, int roff1,
                      int* cur, int* off, float2* pack, int nrows, int* bsums)
{
    cudaMemsetAsync(cur, 0, (size_t)nrows * sizeof(int), 0);
    hist_kernel<<<(n0 + 255) / 256, 256>>>((const int*)rows0, n0, cur, roff0);
    if (rows1)
        hist_kernel<<<(n1 + 255) / 256, 256>>>((const int*)rows1, n1, cur, roff1);

    int nb = (nrows + 1023) / 1024;
    scan_phase1<<<nb, 1024>>>(cur, nrows, bsums);
    scan_phase2<<<1, 256>>>(bsums, nb, off, nrows);
    scan_phase3<<<nb, 1024>>>(cur, nrows, bsums, off);

    cudaMemcpyAsync(cur, off, (size_t)nrows * sizeof(int),
                    cudaMemcpyDeviceToDevice, 0);

    scatter_kernel<<<(n0 + 255) / 256, 256>>>((const int*)rows0, (const int*)cols0,
                                              (const float*)vals0, n0, cur, pack, roff0);
    if (rows1)
        scatter_kernel<<<(n1 + 255) / 256, 256>>>((const int*)rows1, (const int*)cols1,
                                                  (const float*)vals1, n1, cur, pack, roff1);
}

extern "C" void kernel_launch(void* const* d_in, const int* in_sizes, int n_in,
                              void* d_out, int out_size)
{
    const void* u2u_r  = d_in[0];  const void* u2u_c  = d_in[1];  const void* u2u_v  = d_in[2];
    const void* u2i_r0 = d_in[3];  const void* u2i_c0 = d_in[4];  const void* u2i_v0 = d_in[5];
    const void* u2i_r1 = d_in[6];  const void* u2i_c1 = d_in[7];  const void* u2i_v1 = d_in[8];
    const void* i2u_r0 = d_in[9];  const void* i2u_c0 = d_in[10]; const void* i2u_v0 = d_in[11];
    const void* i2u_r1 = d_in[12]; const void* i2u_c1 = d_in[13]; const void* i2u_v1 = d_in[14];
    const void* i2i_r  = d_in[15]; const void* i2i_c  = d_in[16]; const void* i2i_v  = d_in[17];
    const float* user_embs = (const float*)d_in[18];
    const float* item_embs = (const float*)d_in[19];
    const float* W_u       = (const float*)d_in[20];
    const float* W_v       = (const float*)d_in[21];

    const int E_uu  = in_sizes[0];
    const int E_ui0 = in_sizes[3], E_ui1 = in_sizes[6];
    const int E_iu0 = in_sizes[9], E_iu1 = in_sizes[12];
    const int E_ii  = in_sizes[15];

    float* out_user = (float*)d_out;
    float* out_item = (float*)d_out + (size_t)NUM_U * (KTYP * DIM);

    __half2 *ueh, *ieh, *ub1h, *ib1h;
    float2 *pA, *pB, *pC, *pD;
    int *oA, *oB, *oC, *oD, *cA, *cB, *cC, *cD, *bs;
    cudaGetSymbolAddress((void**)&ueh, g_ueh);
    cudaGetSymbolAddress((void**)&ieh, g_ieh);
    cudaGetSymbolAddress((void**)&ub1h, g_ub1h);
    cudaGetSymbolAddress((void**)&ib1h, g_ib1h);
    cudaGetSymbolAddress((void**)&pA, g_packA);
    cudaGetSymbolAddress((void**)&pB, g_packB);
    cudaGetSymbolAddress((void**)&pC, g_packC);
    cudaGetSymbolAddress((void**)&pD, g_packD);
    cudaGetSymbolAddress((void**)&oA, g_offA);
    cudaGetSymbolAddress((void**)&oB, g_offB);
    cudaGetSymbolAddress((void**)&oC, g_offC);
    cudaGetSymbolAddress((void**)&oD, g_offD);
    cudaGetSymbolAddress((void**)&cA, g_curA);
    cudaGetSymbolAddress((void**)&cB, g_curB);
    cudaGetSymbolAddress((void**)&cC, g_curC);
    cudaGetSymbolAddress((void**)&cD, g_curD);
    cudaGetSymbolAddress((void**)&bs, g_bsums);

    // ---- convert embedding tables to half ----
    {
        long long up = (long long)KTYP * NUM_U * 32;   // half2 count
        long long ip = (long long)KTYP * NUM_I * 32;
        convert_kernel<<<(int)((up + 255) / 256), 256>>>(
            (const float2*)user_embs, ueh, up);
        convert_kernel<<<(int)((ip + 255) / 256), 256>>>(
            (const float2*)item_embs, ieh, ip);
    }

    // ---- build the 4 CSR structures ----
    build_csr(u2u_r, u2u_c, u2u_v, E_uu, 0,
              nullptr, nullptr, nullptr, 0, 0, cA, oA, pA, NUM_U, bs);
    build_csr(u2i_r0, u2i_c0, u2i_v0, E_ui0, 0,
              u2i_r1, u2i_c1, u2i_v1, E_ui1, NUM_U / 2, cB, oB, pB, NUM_U, bs);
    build_csr(i2i_r, i2i_c, i2i_v, E_ii, 0,
              nullptr, nullptr, nullptr, 0, 0, cC, oC, pC, NUM_I, bs);
    build_csr(i2u_r0, i2u_c0, i2u_v0, E_iu0, 0,
              i2u_r1, i2u_c1, i2u_v1, E_iu1, NUM_I / 2, cD, oD, pD, NUM_I, bs);

    const int TPB = 256;                       // 8 warps = 8 rows / block
    const int gu = (NUM_U + 7) / 8;
    const int gi = (NUM_I + 7) / 8;

    for (int k = 0; k < KTYP; k++) {
        const float*   ue0f = user_embs + (size_t)k * NUM_U * DIM;
        const float*   ie0f = item_embs + (size_t)k * NUM_I * DIM;
        const __half2* ue0h = ueh + (size_t)k * NUM_U * 32;
        const __half2* ie0h = ieh + (size_t)k * NUM_I * 32;

        // layer 1 (half in, half out)
        spmm_dual_h<<<gu, TPB>>>(oA, pA, ue0h, oB, pB, ie0h, ub1h, NUM_U);
        spmm_dual_h<<<gi, TPB>>>(oC, pC, ie0h, oD, pD, ue0h, ib1h, NUM_I);

        // layer 2 fused with mean + GEMM + ReLU (fp32 out)
        spmm_fused<<<gu, TPB>>>(oA, pA, ub1h, oB, pB, ib1h,
                                ue0f, ub1h, W_u + (size_t)k * DIM * DIM,
                                out_user, NUM_U, KTYP * DIM, k * DIM);
        spmm_fused<<<gi, TPB>>>(oC, pC, ib1h, oD, pD, ub1h,
                                ie0f, ib1h, W_v + (size_t)k * DIM * DIM,
                                out_item, NUM_I, KTYP * DIM, k * DIM);
    }
}